// round 4
// baseline (speedup 1.0000x reference)
#include <cuda_runtime.h>
#include <stdint.h>

#define NMAX 8192
#define WORDS 256          /* NMAX/32 */
#define EC    256          /* max stored cols per row (clamped) */
#define SLICES 16
#define W_IMG 1920.0f
#define H_IMG 1080.0f

// ---------------- device scratch ----------------
__device__ int g_rankp[SLICES][NMAX];
__device__ uint16_t g_ecol[NMAX][EC];         // earlier-neighbor col indices per row
__device__ int g_ecnt[NMAX];
__device__ float4 g_abox[NMAX];               // clipped x1,y1,x2+1,y2+1
__device__ float4 g_obox[NMAX];               // clipped x1,y1,x2,y2
__device__ float g_s[NMAX], g_area[NMAX], g_by2[NMAX];
__device__ uint32_t g_head[WORDS];
__device__ int g_cluster[NMAX];
__device__ int g_cnt[NMAX];
__device__ float g_prob[NMAX];
__device__ uint32_t g_y2bits[NMAX];
__device__ int g_first[NMAX];
__device__ int g_nm;

__device__ __forceinline__ unsigned long long skey(const float* __restrict__ s, int i)
{
    return (((unsigned long long)(~__float_as_uint(s[i]))) << 32) | (uint32_t)i;
}

// ---------------- K1: O(n^2) partial rank, 512-key tiles, 2 keys/thread --------
__global__ void __launch_bounds__(256) k_rank(const float* __restrict__ scores, int n)
{
    __shared__ unsigned long long sk[512];
    int base = blockIdx.y * 512;
    for (int t = threadIdx.x; t < 512; t += 256)
        sk[t] = (base + t < n) ? skey(scores, base + t) : 0xFFFFFFFFFFFFFFFFULL;
    __syncthreads();
    int i0 = blockIdx.x * 512 + threadIdx.x;
    int i1 = i0 + 256;
    unsigned long long a0 = (i0 < n) ? skey(scores, i0) : 0ULL;
    unsigned long long a1 = (i1 < n) ? skey(scores, i1) : 0ULL;
    int c0 = 0, c1 = 0;
    #pragma unroll 8
    for (int q = 0; q < 512; q++) {
        unsigned long long v = sk[q];
        c0 += (v < a0); c1 += (v < a1);
    }
    if (i0 < n) g_rankp[blockIdx.y][i0] = c0;
    if (i1 < n) g_rankp[blockIdx.y][i1] = c1;
}

// ---------------- K2: scatter into sorted order + per-index init ---------------
__global__ void k_gather(const float* __restrict__ boxes, const float* __restrict__ scores,
                         const void* __restrict__ nmp, int n, int slices)
{
    int i = blockIdx.x * blockDim.x + threadIdx.x;
    if (i >= n) return;
    int r = 0;
    for (int k = 0; k < slices; k++) r += g_rankp[k][i];
    float x1 = boxes[i * 4 + 0], y1 = boxes[i * 4 + 1];
    float x2 = boxes[i * 4 + 2], y2 = boxes[i * 4 + 3];
    x1 = fminf(fmaxf(x1, 0.0f), W_IMG);
    y1 = fminf(fmaxf(y1, 0.0f), H_IMG);
    x2 = fminf(fmaxf(x2, 0.0f), W_IMG);
    y2 = fminf(fmaxf(y2, 0.0f), H_IMG);
    g_obox[r] = make_float4(x1, y1, x2, y2);
    g_abox[r] = make_float4(x1, y1, x2 + 1.0f, y2 + 1.0f);
    g_by2[r] = y2;
    g_s[r] = scores[i];
    g_area[r] = ((x2 - x1) + 1.0f) * ((y2 - y1) + 1.0f);
    g_ecnt[i] = 0; g_cnt[i] = 0; g_prob[i] = 0.0f; g_y2bits[i] = 0u; g_first[i] = n;
    if (i == 0) {
        int iv = ((const int*)nmp)[0];
        float fv = ((const float*)nmp)[0];
        g_nm = (iv > 0 && iv < 1000000) ? iv : (int)fv;
    }
}

// ---------------- K3: lower-triangle adjacency -> per-row col lists ------------
// tile = 64 rows x 512 cols; 256 threads (8 warps x 8 rows)
__global__ void __launch_bounds__(256) k_adj(int n)
{
    int rem = blockIdx.x, rt = 0;
    for (;;) { int cnt = (rt >> 3) + 1; if (rem < cnt) break; rem -= cnt; rt++; }
    int rowBase = rt * 64, colBase = rem * 512;

    __shared__ float4 cb[512]; __shared__ float ca[512];
    __shared__ float4 rb[64];  __shared__ float ra[64];

    for (int t = threadIdx.x; t < 512; t += 256) {
        int c = colBase + t;
        if (c < n) { cb[t] = g_abox[c]; ca[t] = g_area[c]; }
        else       { cb[t] = make_float4(2e9f, 2e9f, -2e9f, -2e9f); ca[t] = 1.0f; }
    }
    for (int t = threadIdx.x; t < 64; t += 256) {
        int r = rowBase + t; if (r >= n) r = n - 1;
        rb[t] = g_abox[r]; ra[t] = g_area[r];
    }
    __syncthreads();

    int warp = threadIdx.x >> 5, lane = threadIdx.x & 31;
    int rl0 = warp * 8;

    for (int grp = 0; grp < 2; grp++) {
        int rl = rl0 + grp * 4;
        float4 A[4]; float aa[4];
        #pragma unroll
        for (int k = 0; k < 4; k++) { A[k] = rb[rl + k]; aa[k] = ra[rl + k]; }
        int row0 = rowBase + rl;
        for (int wi = 0; wi < 16; wi++) {
            int cwb = colBase + wi * 32;
            if (cwb > row0 + 3) continue;              // fully above diagonal (warp-uniform)
            float4 B = cb[wi * 32 + lane];
            float ab = ca[wi * 32 + lane];
            #pragma unroll
            for (int k = 0; k < 4; k++) {
                int row = row0 + k;
                if (cwb > row || row >= n) continue;   // warp-uniform
                float w = fmaxf(fminf(A[k].z, B.z) - fmaxf(A[k].x, B.x), 0.0f);
                float h = fmaxf(fminf(A[k].w, B.w) - fmaxf(A[k].y, B.y), 0.0f);
                float inter = w * h;
                float den = (aa[k] + ab) - inter;
                unsigned bits = __ballot_sync(0xffffffffu, inter + inter > den);
                int d = row - cwb;
                if (d < 32) bits &= (1u << d) - 1u;    // strictly below row
                if (lane == 0 && bits) {
                    while (bits) {
                        int b = __ffs(bits) - 1; bits &= bits - 1;
                        int pos = atomicAdd(&g_ecnt[row], 1);
                        if (pos < EC) g_ecol[row][pos] = (uint16_t)(cwb + b);
                    }
                }
            }
        }
    }
}

// ---------------- K4: head resolution (1 block, 256 threads, 256-row chunks) ---
#define PROC_EXT(col) { int cc=(col); if (cc < base) dead |= (headb[cc>>5] >> (cc&31)) & 1u; }
#define PROC_IN(col)  { int cc=(col); if (cc >= base) { int d=cc-base; conf |= (actw[d>>5] >> (d&31)) & 1u; } }

__global__ void __launch_bounds__(256) k_scan(int n)
{
    __shared__ uint32_t headb[WORDS];
    __shared__ uint4 scA[256], scB[256];
    __shared__ int scnt[256];
    __shared__ uint32_t actw[8], confw[8], hc[8];

    int tid = threadIdx.x, lane = tid & 31, warp = tid >> 5;
    for (int t = tid; t < WORDS; t += 256) headb[t] = 0u;

    // prefetch chunk 0
    const uint4 z4 = make_uint4(0,0,0,0);
    int pcnt = (tid < n) ? g_ecnt[tid] : 0;
    uint4 pa = z4, pb = z4;
    if (tid < n && pcnt > 0) {
        pa = *(const uint4*)g_ecol[tid];
        if (pcnt > 8) pb = *((const uint4*)g_ecol[tid] + 1);
    }
    __syncthreads();

    int chunks = (n + 255) >> 8;
    for (int c = 0; c < chunks; c++) {
        int base = c << 8;
        int j = base + tid;
        int cnt = pcnt; uint4 ea = pa, eb = pb;

        // prefetch next chunk
        int jn = j + 256;
        pcnt = (jn < n) ? g_ecnt[jn] : 0;
        pa = z4; pb = z4;
        if (jn < n && pcnt > 0) {
            pa = *(const uint4*)g_ecol[jn];
            if (pcnt > 8) pb = *((const uint4*)g_ecol[jn] + 1);
        }

        // --- phase 1: external (earlier-chunk) head test ---
        uint32_t dead = 0u;
        uint32_t wv[8] = {ea.x, ea.y, ea.z, ea.w, eb.x, eb.y, eb.z, eb.w};
        int cr = cnt < 16 ? cnt : 16;
        #pragma unroll
        for (int q = 0; q < 8; q++) {
            if (2*q   < cr) PROC_EXT((int)(wv[q] & 0xffffu));
            if (2*q+1 < cr) PROC_EXT((int)(wv[q] >> 16));
        }
        if (cnt > 16) {
            int lim = cnt < EC ? cnt : EC;
            for (int q = 16; q < lim; q++) PROC_EXT((int)g_ecol[j][q]);
        }
        bool active = (j < n) && !dead;
        scA[tid] = ea; scB[tid] = eb; scnt[tid] = cnt;
        uint32_t ab = __ballot_sync(0xffffffffu, active);
        if (lane == 0) actw[warp] = ab;
        __syncthreads();

        // --- phase 2: in-chunk conflict test ---
        uint32_t conf = 0u;
        if (active) {
            #pragma unroll
            for (int q = 0; q < 8; q++) {
                if (2*q   < cr) PROC_IN((int)(wv[q] & 0xffffu));
                if (2*q+1 < cr) PROC_IN((int)(wv[q] >> 16));
            }
            if (cnt > 16) conf = 1u;   // force serial resolution (rare)
        }
        uint32_t cb2 = __ballot_sync(0xffffffffu, active && conf);
        if (lane == 0) confw[warp] = cb2;
        __syncthreads();

        // --- phase 3: serial resolution of conflicted rows ---
        if (tid == 0) {
            #pragma unroll
            for (int k = 0; k < 8; k++) hc[k] = actw[k] & ~confw[k];
            for (int k = 0; k < 8; k++) {
                uint32_t m = confw[k];
                while (m) {
                    int b = __ffs(m) - 1; m &= m - 1;
                    int jj = k * 32 + b;
                    int cn = scnt[jj];
                    uint4 xa = scA[jj], xb = scB[jj];
                    uint32_t xv[8] = {xa.x, xa.y, xa.z, xa.w, xb.x, xb.y, xb.z, xb.w};
                    int cr2 = cn < 16 ? cn : 16;
                    uint32_t dd = 0u;
                    for (int q = 0; q < cr2; q++) {
                        int col = (q & 1) ? (int)(xv[q >> 1] >> 16) : (int)(xv[q >> 1] & 0xffffu);
                        if (col >= base) { int d = col - base; dd |= (hc[d >> 5] >> (d & 31)) & 1u; }
                    }
                    if (cn > 16) {
                        int lim = cn < EC ? cn : EC;
                        int row = base + jj;
                        for (int q = 16; q < lim; q++) {
                            int col = (int)g_ecol[row][q];
                            if (col >= base) { int d = col - base; dd |= (hc[d >> 5] >> (d & 31)) & 1u; }
                        }
                    }
                    if (!dd) hc[k] |= 1u << b;
                }
            }
            #pragma unroll
            for (int k = 0; k < 8; k++) headb[(c << 3) + k] = hc[k];
        }
        __syncthreads();
    }
    for (int t = tid; t < WORDS; t += 256) g_head[t] = headb[t];
}

// ---------------- K5: cluster assignment via col list --------------------------
__global__ void k_assign(int n)
{
    __shared__ uint32_t hh[WORDS];
    for (int t = threadIdx.x; t < WORDS; t += blockDim.x) hh[t] = g_head[t];
    __syncthreads();
    int j = blockIdx.x * blockDim.x + threadIdx.x;
    if (j >= n) return;
    int cnt = g_ecnt[j]; if (cnt > EC) cnt = EC;
    int best = 0x7fffffff;
    for (int q = 0; q < cnt; q++) {
        int col = (int)g_ecol[j][q];
        if ((hh[col >> 5] >> (col & 31)) & 1u) { if (col < best) best = col; }
    }
    int cf = (best == 0x7fffffff) ? j : best;
    g_cluster[j] = cf;
    atomicAdd(&g_cnt[cf], 1);
    atomicAdd(&g_prob[cf], g_s[j]);
    atomicMax(&g_y2bits[cf], __float_as_uint(g_by2[j]));   // by2 >= 0 -> bit-ordered
}

// ---------------- K6: first pick per cluster ------------------------------------
__global__ void k_first(int n)
{
    int j = blockIdx.x * blockDim.x + threadIdx.x;
    if (j >= n) return;
    int c = g_cluster[j];
    float mx = __uint_as_float(g_y2bits[c]);
    if (g_by2[j] >= mx) atomicMin(&g_first[c], j);
}

// ---------------- K7: write output ----------------------------------------------
__global__ void k_out(float* __restrict__ out, int n, int out_size)
{
    int i = blockIdx.x * blockDim.x + threadIdx.x;
    if (i < n) {
        int c = g_cluster[i];
        float nmf = (float)g_nm;
        bool keep = (i == g_first[c]) && ((float)g_cnt[c] >= nmf / 3.0f);
        float so = g_prob[c] / nmf;
        float4 b = g_obox[i];
        out[i * 5 + 0] = keep ? b.x : 0.0f;
        out[i * 5 + 1] = keep ? b.y : 0.0f;
        out[i * 5 + 2] = keep ? b.z : 0.0f;
        out[i * 5 + 3] = keep ? b.w : 0.0f;
        out[i * 5 + 4] = keep ? so : 0.0f;
        if (out_size >= 6 * n) out[5 * n + i] = keep ? 1.0f : 0.0f;
    }
    int stride = gridDim.x * blockDim.x;
    for (int t = 6 * n + i; t < out_size; t += stride) out[t] = 0.0f;
}

// ---------------- launcher -------------------------------------------------------
extern "C" void kernel_launch(void* const* d_in, const int* in_sizes, int n_in,
                              void* d_out, int out_size)
{
    const float* boxes  = (const float*)d_in[0];
    const float* scores = (const float*)d_in[1];
    const void*  nmp    = d_in[2];
    int n = in_sizes[1];
    if (n > NMAX) n = NMAX;

    int nb = (n + 255) / 256;
    int slices = (n + 511) / 512;            // <= SLICES
    dim3 rg((n + 511) / 512, slices);
    k_rank<<<rg, 256>>>(scores, n);
    k_gather<<<nb, 256>>>(boxes, scores, nmp, n, slices);

    int rowTiles = (n + 63) / 64;
    int tiles = 0;
    for (int rt = 0; rt < rowTiles; rt++) tiles += (rt >> 3) + 1;
    k_adj<<<tiles, 256>>>(n);

    k_scan<<<1, 256>>>(n);
    k_assign<<<nb, 256>>>(n);
    k_first<<<nb, 256>>>(n);
    k_out<<<nb, 256>>>((float*)d_out, n, out_size);
}

// round 7
// speedup vs baseline: 1.8582x; 1.8582x over previous
#include <cuda_runtime.h>
#include <stdint.h>

#define NMAX 8192
#define WORDS 256          /* NMAX/32 */
#define EC    256          /* max stored cols per row (clamped) */
#define SLICES 16
#define W_IMG 1920.0f
#define H_IMG 1080.0f

// ---------------- device scratch ----------------
__device__ int g_rankp[SLICES][NMAX];
__device__ uint16_t g_ecol[NMAX][EC];         // earlier-neighbor col indices per row
__device__ int g_ecnt[NMAX];
__device__ float4 g_abox[NMAX];               // clipped x1,y1,x2+1,y2+1
__device__ float4 g_obox[NMAX];               // clipped x1,y1,x2,y2
__device__ float g_s[NMAX], g_area[NMAX], g_by2[NMAX];
__device__ uint32_t g_head[WORDS];
__device__ int g_cluster[NMAX];
__device__ int g_cnt[NMAX];
__device__ float g_prob[NMAX];
__device__ uint32_t g_y2bits[NMAX];
__device__ int g_first[NMAX];
__device__ int g_nm;

__device__ __forceinline__ unsigned long long skey(const float* __restrict__ s, int i)
{
    return (((unsigned long long)(~__float_as_uint(s[i]))) << 32) | (uint32_t)i;
}

// ---------------- K1: O(n^2) partial rank, 512-key tiles, 2 keys/thread --------
__global__ void __launch_bounds__(256) k_rank(const float* __restrict__ scores, int n)
{
    __shared__ unsigned long long sk[512];
    int base = blockIdx.y * 512;
    for (int t = threadIdx.x; t < 512; t += 256)
        sk[t] = (base + t < n) ? skey(scores, base + t) : 0xFFFFFFFFFFFFFFFFULL;
    __syncthreads();
    int i0 = blockIdx.x * 512 + threadIdx.x;
    int i1 = i0 + 256;
    unsigned long long a0 = (i0 < n) ? skey(scores, i0) : 0ULL;
    unsigned long long a1 = (i1 < n) ? skey(scores, i1) : 0ULL;
    int c0 = 0, c1 = 0;
    #pragma unroll 8
    for (int q = 0; q < 512; q++) {
        unsigned long long v = sk[q];
        c0 += (v < a0); c1 += (v < a1);
    }
    if (i0 < n) g_rankp[blockIdx.y][i0] = c0;
    if (i1 < n) g_rankp[blockIdx.y][i1] = c1;
}

// ---------------- K2: scatter into sorted order + per-index init ---------------
__global__ void k_gather(const float* __restrict__ boxes, const float* __restrict__ scores,
                         const void* __restrict__ nmp, int n, int slices)
{
    int i = blockIdx.x * blockDim.x + threadIdx.x;
    if (i >= n) return;
    int r = 0;
    for (int k = 0; k < slices; k++) r += g_rankp[k][i];
    float x1 = boxes[i * 4 + 0], y1 = boxes[i * 4 + 1];
    float x2 = boxes[i * 4 + 2], y2 = boxes[i * 4 + 3];
    x1 = fminf(fmaxf(x1, 0.0f), W_IMG);
    y1 = fminf(fmaxf(y1, 0.0f), H_IMG);
    x2 = fminf(fmaxf(x2, 0.0f), W_IMG);
    y2 = fminf(fmaxf(y2, 0.0f), H_IMG);
    g_obox[r] = make_float4(x1, y1, x2, y2);
    g_abox[r] = make_float4(x1, y1, x2 + 1.0f, y2 + 1.0f);
    g_by2[r] = y2;
    g_s[r] = scores[i];
    g_area[r] = ((x2 - x1) + 1.0f) * ((y2 - y1) + 1.0f);
    g_ecnt[i] = 0; g_cnt[i] = 0; g_prob[i] = 0.0f; g_y2bits[i] = 0u; g_first[i] = n;
    if (i == 0) {
        int iv = ((const int*)nmp)[0];
        float fv = ((const float*)nmp)[0];
        g_nm = (iv > 0 && iv < 1000000) ? iv : (int)fv;
    }
}

// ---------------- K3: lower-triangle adjacency -> per-row col lists ------------
// tile = 64 rows x 512 cols; 256 threads (8 warps x 8 rows)
__global__ void __launch_bounds__(256) k_adj(int n)
{
    int rem = blockIdx.x, rt = 0;
    for (;;) { int cnt = (rt >> 3) + 1; if (rem < cnt) break; rem -= cnt; rt++; }
    int rowBase = rt * 64, colBase = rem * 512;

    __shared__ float4 cb[512]; __shared__ float ca[512];
    __shared__ float4 rb[64];  __shared__ float ra[64];

    for (int t = threadIdx.x; t < 512; t += 256) {
        int c = colBase + t;
        if (c < n) { cb[t] = g_abox[c]; ca[t] = g_area[c]; }
        else       { cb[t] = make_float4(2e9f, 2e9f, -2e9f, -2e9f); ca[t] = 1.0f; }
    }
    for (int t = threadIdx.x; t < 64; t += 256) {
        int r = rowBase + t; if (r >= n) r = n - 1;
        rb[t] = g_abox[r]; ra[t] = g_area[r];
    }
    __syncthreads();

    int warp = threadIdx.x >> 5, lane = threadIdx.x & 31;
    int rl0 = warp * 8;

    for (int grp = 0; grp < 2; grp++) {
        int rl = rl0 + grp * 4;
        float4 A[4]; float aa[4];
        #pragma unroll
        for (int k = 0; k < 4; k++) { A[k] = rb[rl + k]; aa[k] = ra[rl + k]; }
        int row0 = rowBase + rl;
        for (int wi = 0; wi < 16; wi++) {
            int cwb = colBase + wi * 32;
            if (cwb > row0 + 3) continue;              // fully above diagonal (warp-uniform)
            float4 B = cb[wi * 32 + lane];
            float ab = ca[wi * 32 + lane];
            #pragma unroll
            for (int k = 0; k < 4; k++) {
                int row = row0 + k;
                if (cwb > row || row >= n) continue;   // warp-uniform
                float w = fmaxf(fminf(A[k].z, B.z) - fmaxf(A[k].x, B.x), 0.0f);
                float h = fmaxf(fminf(A[k].w, B.w) - fmaxf(A[k].y, B.y), 0.0f);
                float inter = w * h;
                float den = (aa[k] + ab) - inter;
                unsigned bits = __ballot_sync(0xffffffffu, inter + inter > den);
                int d = row - cwb;
                if (d < 32) bits &= (1u << d) - 1u;    // strictly below row
                if (lane == 0 && bits) {
                    while (bits) {
                        int b = __ffs(bits) - 1; bits &= bits - 1;
                        int pos = atomicAdd(&g_ecnt[row], 1);
                        if (pos < EC) g_ecol[row][pos] = (uint16_t)(cwb + b);
                    }
                }
            }
        }
    }
}

// ---------------- K4: head resolution via monotone worklist fixed point --------
__global__ void __launch_bounds__(1024) k_scan(int n)
{
    __shared__ uint32_t headb[WORDS];
    __shared__ uint32_t deadb[WORDS];
    __shared__ uint16_t wl[2][NMAX];          // 32 KB
    __shared__ int wcnt[2];

    int tid = threadIdx.x, lane = tid & 31;
    for (int t = tid; t < WORDS; t += 1024) { headb[t] = 0u; deadb[t] = 0u; }
    if (tid < 2) wcnt[tid] = 0;
    __syncthreads();

    // pass 0: rows with no earlier neighbors are heads; rest -> worklist
    for (int j0 = tid; j0 < ((n + 31) & ~31); j0 += 1024) {
        bool hasrow = (j0 < n);
        int cnt = hasrow ? g_ecnt[j0] : 0;
        bool work = hasrow && (cnt > 0);
        if (hasrow && cnt == 0) atomicOr(&headb[j0 >> 5], 1u << (j0 & 31));
        unsigned wb = __ballot_sync(0xffffffffu, work);
        if (work) {
            int leader = __ffs(wb) - 1;
            int basep = 0;
            if (lane == leader) basep = atomicAdd(&wcnt[0], __popc(wb));
            basep = __shfl_sync(wb, basep, leader);    // mask = participating lanes only
            int off = __popc(wb & ((1u << lane) - 1u));
            wl[0][basep + off] = (uint16_t)j0;
        }
    }
    __syncthreads();

    int cur = 0;
    for (int pass = 0; pass < NMAX && wcnt[cur] > 0; pass++) {
        int cnt_cur = wcnt[cur];
        int nxt = cur ^ 1;
        for (int q = tid; q < cnt_cur; q += 1024) {
            int j = wl[cur][q];
            int ec = g_ecnt[j]; if (ec > EC) ec = EC;
            bool anyhead = false, allres = true;
            for (int e = 0; e < ec; e++) {
                int col = (int)g_ecol[j][e];
                uint32_t m = 1u << (col & 31);
                if (headb[col >> 5] & m) { anyhead = true; break; }
                if (!(deadb[col >> 5] & m)) allres = false;
            }
            if (anyhead) atomicOr(&deadb[j >> 5], 1u << (j & 31));
            else if (allres) atomicOr(&headb[j >> 5], 1u << (j & 31));
            else { int p = atomicAdd(&wcnt[nxt], 1); wl[nxt][p] = (uint16_t)j; }
        }
        __syncthreads();
        if (tid == 0) wcnt[cur] = 0;
        cur = nxt;
        __syncthreads();
    }
    for (int t = tid; t < WORDS; t += 1024) g_head[t] = headb[t];
}

// ---------------- K5: cluster assignment via col list --------------------------
__global__ void k_assign(int n)
{
    __shared__ uint32_t hh[WORDS];
    for (int t = threadIdx.x; t < WORDS; t += blockDim.x) hh[t] = g_head[t];
    __syncthreads();
    int j = blockIdx.x * blockDim.x + threadIdx.x;
    if (j >= n) return;
    int cnt = g_ecnt[j]; if (cnt > EC) cnt = EC;
    int best = 0x7fffffff;
    for (int q = 0; q < cnt; q++) {
        int col = (int)g_ecol[j][q];
        if ((hh[col >> 5] >> (col & 31)) & 1u) { if (col < best) best = col; }
    }
    int cf = (best == 0x7fffffff) ? j : best;
    g_cluster[j] = cf;
    atomicAdd(&g_cnt[cf], 1);
    atomicAdd(&g_prob[cf], g_s[j]);
    atomicMax(&g_y2bits[cf], __float_as_uint(g_by2[j]));   // by2 >= 0 -> bit-ordered
}

// ---------------- K6: first pick per cluster ------------------------------------
__global__ void k_first(int n)
{
    int j = blockIdx.x * blockDim.x + threadIdx.x;
    if (j >= n) return;
    int c = g_cluster[j];
    float mx = __uint_as_float(g_y2bits[c]);
    if (g_by2[j] >= mx) atomicMin(&g_first[c], j);
}

// ---------------- K7: write output ----------------------------------------------
__global__ void k_out(float* __restrict__ out, int n, int out_size)
{
    int i = blockIdx.x * blockDim.x + threadIdx.x;
    if (i < n) {
        int c = g_cluster[i];
        float nmf = (float)g_nm;
        bool keep = (i == g_first[c]) && ((float)g_cnt[c] >= nmf / 3.0f);
        float so = g_prob[c] / nmf;
        float4 b = g_obox[i];
        out[i * 5 + 0] = keep ? b.x : 0.0f;
        out[i * 5 + 1] = keep ? b.y : 0.0f;
        out[i * 5 + 2] = keep ? b.z : 0.0f;
        out[i * 5 + 3] = keep ? b.w : 0.0f;
        out[i * 5 + 4] = keep ? so : 0.0f;
        if (out_size >= 6 * n) out[5 * n + i] = keep ? 1.0f : 0.0f;
    }
    int stride = gridDim.x * blockDim.x;
    for (int t = 6 * n + i; t < out_size; t += stride) out[t] = 0.0f;
}

// ---------------- launcher -------------------------------------------------------
extern "C" void kernel_launch(void* const* d_in, const int* in_sizes, int n_in,
                              void* d_out, int out_size)
{
    const float* boxes  = (const float*)d_in[0];
    const float* scores = (const float*)d_in[1];
    const void*  nmp    = d_in[2];
    int n = in_sizes[1];
    if (n > NMAX) n = NMAX;

    int nb = (n + 255) / 256;
    int slices = (n + 511) / 512;            // <= SLICES
    dim3 rg((n + 511) / 512, slices);
    k_rank<<<rg, 256>>>(scores, n);
    k_gather<<<nb, 256>>>(boxes, scores, nmp, n, slices);

    int rowTiles = (n + 63) / 64;
    int tiles = 0;
    for (int rt = 0; rt < rowTiles; rt++) tiles += (rt >> 3) + 1;
    k_adj<<<tiles, 256>>>(n);

    k_scan<<<1, 1024>>>(n);
    k_assign<<<nb, 256>>>(n);
    k_first<<<nb, 256>>>(n);
    k_out<<<nb, 256>>>((float*)d_out, n, out_size);
}

// round 8
// speedup vs baseline: 1.8965x; 1.0206x over previous
#include <cuda_runtime.h>
#include <stdint.h>

#define NMAX 8192
#define WORDS 256          /* NMAX/32 */
#define EC    256          /* max stored cols per row (clamped) */
#define SLICES 16
#define W_IMG 1920.0f
#define H_IMG 1080.0f

// ---------------- device scratch ----------------
__device__ int g_rankp[SLICES][NMAX];
__device__ uint16_t g_ecol[NMAX][EC];         // earlier-neighbor col indices per row
__device__ int g_ecnt[NMAX];
__device__ float4 g_abox[NMAX];               // clipped x1,y1,x2+1,y2+1
__device__ float4 g_obox[NMAX];               // clipped x1,y1,x2,y2
__device__ float g_s[NMAX], g_area[NMAX], g_by2[NMAX];
__device__ uint32_t g_head[WORDS];
__device__ int g_cluster[NMAX];
__device__ int g_cnt[NMAX];
__device__ float g_prob[NMAX];
__device__ unsigned long long g_pick[NMAX];   // (y2bits<<32) | (n - j)
__device__ int g_nm;

__device__ __forceinline__ unsigned long long skey(const float* __restrict__ s, int i)
{
    return (((unsigned long long)(~__float_as_uint(s[i]))) << 32) | (uint32_t)i;
}

// ---------------- K1: O(n^2) partial rank, 512-key tiles, 2 keys/thread --------
__global__ void __launch_bounds__(256) k_rank(const float* __restrict__ scores, int n)
{
    __shared__ unsigned long long sk[512];
    int base = blockIdx.y * 512;
    for (int t = threadIdx.x; t < 512; t += 256)
        sk[t] = (base + t < n) ? skey(scores, base + t) : 0xFFFFFFFFFFFFFFFFULL;
    __syncthreads();
    int i0 = blockIdx.x * 512 + threadIdx.x;
    int i1 = i0 + 256;
    unsigned long long a0 = (i0 < n) ? skey(scores, i0) : 0ULL;
    unsigned long long a1 = (i1 < n) ? skey(scores, i1) : 0ULL;
    int c0 = 0, c1 = 0;
    #pragma unroll 8
    for (int q = 0; q < 512; q++) {
        unsigned long long v = sk[q];
        c0 += (v < a0); c1 += (v < a1);
    }
    if (i0 < n) g_rankp[blockIdx.y][i0] = c0;
    if (i1 < n) g_rankp[blockIdx.y][i1] = c1;
}

// ---------------- K2: scatter into sorted order + per-index init ---------------
__global__ void k_gather(const float* __restrict__ boxes, const float* __restrict__ scores,
                         const void* __restrict__ nmp, int n, int slices)
{
    int i = blockIdx.x * blockDim.x + threadIdx.x;
    if (i >= n) return;
    int r = 0;
    for (int k = 0; k < slices; k++) r += g_rankp[k][i];
    float4 bx = ((const float4*)boxes)[i];
    float x1 = fminf(fmaxf(bx.x, 0.0f), W_IMG);
    float y1 = fminf(fmaxf(bx.y, 0.0f), H_IMG);
    float x2 = fminf(fmaxf(bx.z, 0.0f), W_IMG);
    float y2 = fminf(fmaxf(bx.w, 0.0f), H_IMG);
    g_obox[r] = make_float4(x1, y1, x2, y2);
    g_abox[r] = make_float4(x1, y1, x2 + 1.0f, y2 + 1.0f);
    g_by2[r] = y2;
    g_s[r] = scores[i];
    g_area[r] = ((x2 - x1) + 1.0f) * ((y2 - y1) + 1.0f);
    g_ecnt[i] = 0; g_cnt[i] = 0; g_prob[i] = 0.0f; g_pick[i] = 0ULL;
    if (i == 0) {
        int iv = ((const int*)nmp)[0];
        float fv = ((const float*)nmp)[0];
        g_nm = (iv > 0 && iv < 1000000) ? iv : (int)fv;
    }
}

// ---------------- K3: lower-triangle adjacency -> per-row col lists ------------
// tile = 64 rows x 512 cols; 256 threads (8 warps x 8 rows)
__global__ void __launch_bounds__(256) k_adj(int n)
{
    int rem = blockIdx.x, rt = 0;
    for (;;) { int cnt = (rt >> 3) + 1; if (rem < cnt) break; rem -= cnt; rt++; }
    int rowBase = rt * 64, colBase = rem * 512;

    __shared__ float4 cb[512]; __shared__ float ca[512];
    __shared__ float4 rb[64];  __shared__ float ra[64];

    for (int t = threadIdx.x; t < 512; t += 256) {
        int c = colBase + t;
        if (c < n) { cb[t] = g_abox[c]; ca[t] = g_area[c]; }
        else       { cb[t] = make_float4(2e9f, 2e9f, -2e9f, -2e9f); ca[t] = 1.0f; }
    }
    for (int t = threadIdx.x; t < 64; t += 256) {
        int r = rowBase + t; if (r >= n) r = n - 1;
        rb[t] = g_abox[r]; ra[t] = g_area[r];
    }
    __syncthreads();

    int warp = threadIdx.x >> 5, lane = threadIdx.x & 31;
    int rl0 = warp * 8;

    for (int grp = 0; grp < 2; grp++) {
        int rl = rl0 + grp * 4;
        float4 A[4]; float aa[4];
        #pragma unroll
        for (int k = 0; k < 4; k++) { A[k] = rb[rl + k]; aa[k] = ra[rl + k]; }
        int row0 = rowBase + rl;
        for (int wi = 0; wi < 16; wi++) {
            int cwb = colBase + wi * 32;
            if (cwb > row0 + 3) continue;              // fully above diagonal (warp-uniform)
            float4 B = cb[wi * 32 + lane];
            float ab = ca[wi * 32 + lane];
            #pragma unroll
            for (int k = 0; k < 4; k++) {
                int row = row0 + k;
                if (cwb > row || row >= n) continue;   // warp-uniform
                float w = fmaxf(fminf(A[k].z, B.z) - fmaxf(A[k].x, B.x), 0.0f);
                float h = fmaxf(fminf(A[k].w, B.w) - fmaxf(A[k].y, B.y), 0.0f);
                float inter = w * h;
                float den = (aa[k] + ab) - inter;
                unsigned bits = __ballot_sync(0xffffffffu, inter + inter > den);
                int d = row - cwb;
                if (d < 32) bits &= (1u << d) - 1u;    // strictly below row
                if (lane == 0 && bits) {
                    while (bits) {
                        int b = __ffs(bits) - 1; bits &= bits - 1;
                        int pos = atomicAdd(&g_ecnt[row], 1);
                        if (pos < EC) g_ecol[row][pos] = (uint16_t)(cwb + b);
                    }
                }
            }
        }
    }
}

// ---------------- K4: head resolution via monotone worklist fixed point --------
__global__ void __launch_bounds__(1024) k_scan(int n)
{
    __shared__ uint32_t headb[WORDS];
    __shared__ uint32_t decb[WORDS];          // decided = head | dead
    __shared__ uint16_t wl[2][NMAX];          // 32 KB
    __shared__ int wcnt[2];

    int tid = threadIdx.x, lane = tid & 31;
    for (int t = tid; t < WORDS; t += 1024) { headb[t] = 0u; decb[t] = 0u; }
    if (tid < 2) wcnt[tid] = 0;
    __syncthreads();

    // pass 0: rows with no earlier neighbors are heads; rest -> worklist
    for (int j0 = tid; j0 < ((n + 31) & ~31); j0 += 1024) {
        bool hasrow = (j0 < n);
        int cnt = hasrow ? g_ecnt[j0] : 0;
        bool work = hasrow && (cnt > 0);
        if (hasrow && cnt == 0) {
            atomicOr(&headb[j0 >> 5], 1u << (j0 & 31));
            atomicOr(&decb[j0 >> 5], 1u << (j0 & 31));
        }
        unsigned wb = __ballot_sync(0xffffffffu, work);
        if (work) {
            int leader = __ffs(wb) - 1;
            int basep = 0;
            if (lane == leader) basep = atomicAdd(&wcnt[0], __popc(wb));
            basep = __shfl_sync(wb, basep, leader);
            int off = __popc(wb & ((1u << lane) - 1u));
            wl[0][basep + off] = (uint16_t)j0;
        }
    }
    __syncthreads();

    int cur = 0;
    for (int pass = 0; pass < NMAX && wcnt[cur] > 0; pass++) {
        int cnt_cur = wcnt[cur];
        int nxt = cur ^ 1;
        for (int q = tid; q < cnt_cur; q += 1024) {
            int j = wl[cur][q];
            int ec = g_ecnt[j]; if (ec > EC) ec = EC;
            uint4 ev = *(const uint4*)g_ecol[j];       // first 8 cols, one load
            uint32_t cw[4] = {ev.x, ev.y, ev.z, ev.w};
            bool anyhead = false, allres = true;
            int r8 = ec < 8 ? ec : 8;
            #pragma unroll
            for (int e = 0; e < 8; e++) {
                if (e >= r8) break;
                int col = (e & 1) ? (int)(cw[e >> 1] >> 16) : (int)(cw[e >> 1] & 0xffffu);
                uint32_t m = 1u << (col & 31);
                anyhead |= (headb[col >> 5] & m) != 0u;
                allres  &= (decb[col >> 5] & m) != 0u;
            }
            if (!anyhead) {
                for (int e = 8; e < ec; e++) {
                    int col = (int)g_ecol[j][e];
                    uint32_t m = 1u << (col & 31);
                    if (headb[col >> 5] & m) { anyhead = true; break; }
                    if (!(decb[col >> 5] & m)) allres = false;
                }
            }
            if (anyhead) atomicOr(&decb[j >> 5], 1u << (j & 31));            // dead
            else if (allres) {
                atomicOr(&headb[j >> 5], 1u << (j & 31));
                atomicOr(&decb[j >> 5], 1u << (j & 31));
            }
            else { int p = atomicAdd(&wcnt[nxt], 1); wl[nxt][p] = (uint16_t)j; }
        }
        __syncthreads();
        if (tid == 0) wcnt[cur] = 0;
        cur = nxt;
        __syncthreads();
    }
    for (int t = tid; t < WORDS; t += 1024) g_head[t] = headb[t];
}

// ---------------- K5: cluster assignment + all segment reductions --------------
__global__ void k_assign(int n)
{
    __shared__ uint32_t hh[WORDS];
    for (int t = threadIdx.x; t < WORDS; t += blockDim.x) hh[t] = g_head[t];
    __syncthreads();
    int j = blockIdx.x * blockDim.x + threadIdx.x;
    if (j >= n) return;
    int cnt = g_ecnt[j]; if (cnt > EC) cnt = EC;
    int best = 0x7fffffff;
    uint4 ev = *(const uint4*)g_ecol[j];
    uint32_t cw[4] = {ev.x, ev.y, ev.z, ev.w};
    int r8 = cnt < 8 ? cnt : 8;
    #pragma unroll
    for (int e = 0; e < 8; e++) {
        if (e >= r8) break;
        int col = (e & 1) ? (int)(cw[e >> 1] >> 16) : (int)(cw[e >> 1] & 0xffffu);
        if ((hh[col >> 5] >> (col & 31)) & 1u) { if (col < best) best = col; }
    }
    for (int q = 8; q < cnt; q++) {
        int col = (int)g_ecol[j][q];
        if ((hh[col >> 5] >> (col & 31)) & 1u) { if (col < best) best = col; }
    }
    int cf = (best == 0x7fffffff) ? j : best;
    g_cluster[j] = cf;
    atomicAdd(&g_cnt[cf], 1);
    atomicAdd(&g_prob[cf], g_s[j]);
    // segment_max(by2) with min-index tie-break, fused in one 64-bit max
    unsigned long long key = (((unsigned long long)__float_as_uint(g_by2[j])) << 32)
                           | (unsigned long long)(uint32_t)(n - j);
    atomicMax(&g_pick[cf], key);
}

// ---------------- K6: write output ----------------------------------------------
__global__ void k_out(float* __restrict__ out, int n, int out_size)
{
    int i = blockIdx.x * blockDim.x + threadIdx.x;
    if (i < n) {
        int c = g_cluster[i];
        float nmf = (float)g_nm;
        int firstj = n - (int)(uint32_t)(g_pick[c] & 0xffffffffULL);
        bool keep = (i == firstj) && ((float)g_cnt[c] >= nmf / 3.0f);
        float so = g_prob[c] / nmf;
        float4 b = g_obox[i];
        out[i * 5 + 0] = keep ? b.x : 0.0f;
        out[i * 5 + 1] = keep ? b.y : 0.0f;
        out[i * 5 + 2] = keep ? b.z : 0.0f;
        out[i * 5 + 3] = keep ? b.w : 0.0f;
        out[i * 5 + 4] = keep ? so : 0.0f;
        if (out_size >= 6 * n) out[5 * n + i] = keep ? 1.0f : 0.0f;
    }
    int stride = gridDim.x * blockDim.x;
    for (int t = 6 * n + i; t < out_size; t += stride) out[t] = 0.0f;
}

// ---------------- launcher -------------------------------------------------------
extern "C" void kernel_launch(void* const* d_in, const int* in_sizes, int n_in,
                              void* d_out, int out_size)
{
    const float* boxes  = (const float*)d_in[0];
    const float* scores = (const float*)d_in[1];
    const void*  nmp    = d_in[2];
    int n = in_sizes[1];
    if (n > NMAX) n = NMAX;

    int nb = (n + 255) / 256;
    int slices = (n + 511) / 512;            // <= SLICES
    dim3 rg((n + 511) / 512, slices);
    k_rank<<<rg, 256>>>(scores, n);
    k_gather<<<nb, 256>>>(boxes, scores, nmp, n, slices);

    int rowTiles = (n + 63) / 64;
    int tiles = 0;
    for (int rt = 0; rt < rowTiles; rt++) tiles += (rt >> 3) + 1;
    k_adj<<<tiles, 256>>>(n);

    k_scan<<<1, 1024>>>(n);
    k_assign<<<nb, 256>>>(n);
    k_out<<<nb, 256>>>((float*)d_out, n, out_size);
}